// round 6
// baseline (speedup 1.0000x reference)
#include <cuda_runtime.h>

// ---------------------------------------------------------------------------
// Round 6 = Round 5 with the SXOR2X2_RAT algebra bug fixed:
//   tx*ty = NxNy/(DxDy) = NxNy * R      (R = 1/(DxDy))   -- was wrongly R^2.
// The (1-tx^2)(1-ty^2) term keeps R^2 (both denominators squared).
// Everything else unchanged from R5 (80 rot63-feeding xor sites on the fma
// pipe via Eigen-rational tanh + bit-hack/Newton reciprocal; all other sites
// bit-identical to the passing R4 kernel; rot scalings folded exactly).
// ---------------------------------------------------------------------------

typedef unsigned long long p2;   // packed float2 in one 64-bit register pair

#define BCST(h) ((((p2)(h))<<32) | (p2)(h))

#define C5     BCST(0x40A00000u)  //  5.0
#define CN5    BCST(0xC0A00000u)  // -5.0
#define CN2P5  BCST(0xC0200000u)  // -2.5
#define CH     BCST(0x3F000000u)  //  0.5
#define CNH    BCST(0xBF000000u)  // -0.5
#define C1     BCST(0x3F800000u)  //  1.0
#define CN1    BCST(0xBF800000u)  // -1.0
#define C2     BCST(0x40000000u)  //  2.0
#define CN16   BCST(0xBD800000u)  // -1/16
#define CN8    BCST(0xBE000000u)  // -1/8
#define C2P64  BCST(0x5F800000u)  //  2^64
#define C2N64  BCST(0x1F800000u)  //  2^-64
#define C2N32  BCST(0x2F800000u)  //  2^-32
#define C2N24  BCST(0x33800000u)  //  2^-24
#define C2N16  BCST(0x37800000u)  //  2^-16
#define C5_32  BCST(0x30A00000u)  //  5 * 2^-32
#define C5_24  BCST(0x34A00000u)  //  5 * 2^-24
#define SGNM   BCST(0x80000000u)  //  sign mask

__device__ __forceinline__ p2 pk(float lo, float hi) {
    p2 r; asm("mov.b64 %0, {%1, %2};" : "=l"(r) : "f"(lo), "f"(hi)); return r;
}
__device__ __forceinline__ void upk(p2 v, float& lo, float& hi) {
    asm("mov.b64 {%0, %1}, %2;" : "=f"(lo), "=f"(hi) : "l"(v));
}
__device__ __forceinline__ p2 fma2(p2 a, p2 b, p2 c) {
    p2 r; asm("fma.rn.f32x2 %0, %1, %2, %3;" : "=l"(r) : "l"(a), "l"(b), "l"(c)); return r;
}
__device__ __forceinline__ p2 add2(p2 a, p2 b) {
    p2 r; asm("add.rn.f32x2 %0, %1, %2;" : "=l"(r) : "l"(a), "l"(b)); return r;
}
__device__ __forceinline__ p2 mul2(p2 a, p2 b) {
    p2 r; asm("mul.rn.f32x2 %0, %1, %2;" : "=l"(r) : "l"(a), "l"(b)); return r;
}
__device__ __forceinline__ p2 tanh2(p2 z) {
    float a, b; upk(z, a, b);
    asm("tanh.approx.f32 %0, %0;" : "+f"(a));
    asm("tanh.approx.f32 %0, %0;" : "+f"(b));
    return pk(a, b);
}
__device__ __forceinline__ p2 trunc2(p2 z) {
    float a, b; upk(z, a, b);
    return pk(truncf(a), truncf(b));
}
__device__ __forceinline__ p2 xor2(p2 a, p2 b) {
    p2 r; asm("xor.b64 %0, %1, %2;" : "=l"(r) : "l"(a), "l"(b)); return r;
}
// reciprocal seed: per-half 0x7EF311C3 - bits(x)  (alu pipe, ~5-10% rel err)
__device__ __forceinline__ p2 rcp_seed(p2 x) {
    p2 r;
    asm("{\n\t"
        ".reg .b32 lo, hi;\n\t"
        "mov.b64 {lo, hi}, %1;\n\t"
        "sub.u32 lo, 0x7EF311C3, lo;\n\t"
        "sub.u32 hi, 0x7EF311C3, hi;\n\t"
        "mov.b64 %0, {lo, hi};\n\t"
        "}" : "=l"(r) : "l"(x));
    return r;
}

// soft_add, sum s precomputed by caller (possibly via a scale-folding fma):
// out = (s - 0.5) - 0.5*tanh(5s - 5)
__device__ __forceinline__ p2 sadd_pre(p2 s) {
    p2 t = tanh2(fma2(s, C5, CN5));
    return fma2(t, CNH, add2(s, CNH));
}

// soft_xor given precomputed tanh args zx, zy (tanh.approx path):
// r = (1 - tx*ty)/2 - (1-tx^2)(1-ty^2)/16
__device__ __forceinline__ p2 sxor_core(p2 zx, p2 zy) {
    p2 tx = tanh2(zx);
    p2 ty = tanh2(zy);
    p2 r1 = fma2(mul2(tx, ty), CNH, CH);
    p2 a  = fma2(tx, tx, CN1);
    p2 b  = fma2(ty, ty, CN1);
    return fma2(mul2(a, b), CN16, r1);
}

// Eigen ptanh rational: t = z*P6(z^2) / Q3(z^2), valid |z| <= ~7.9, err ~1e-7
#define EA6 (-2.76076847742355e-16f)
#define EA5 ( 2.00018790482477e-13f)
#define EA4 (-8.60467152213735e-11f)
#define EA3 ( 5.12229709037114e-08f)
#define EA2 ( 1.48572235717979e-05f)
#define EA1 ( 6.37261928875436e-04f)
#define EA0 ( 4.89352455891786e-03f)
#define EB3 ( 1.19825839466702e-06f)
#define EB2 ( 1.18534705686654e-04f)
#define EB1 ( 2.26843463243900e-03f)
#define EB0 ( 4.89352518554385e-03f)

__device__ __forceinline__ void rat_tanh_nd(p2 z, p2& N, p2& D,
                                            p2 A6, p2 A5, p2 A4, p2 A3,
                                            p2 A2, p2 A1, p2 A0,
                                            p2 B3, p2 B2, p2 B1, p2 B0) {
    p2 u = mul2(z, z);
    p2 n = fma2(u, A6, A5);
    n = fma2(u, n, A4);
    n = fma2(u, n, A3);
    n = fma2(u, n, A2);
    n = fma2(u, n, A1);
    n = fma2(u, n, A0);
    N = mul2(z, n);
    p2 d = fma2(u, B3, B2);
    d = fma2(u, d, B1);
    D = fma2(u, d, B0);
}

// doubled soft_xor (feeds rot63), MUFU-free accurate path:
// tx=Nx/Dx, ty=Ny/Dy; 2*xor = (1 - tx*ty) - (1-tx^2)(1-ty^2)/8
//   = (1 - NxNy*R) - (Dx^2-Nx^2)(Dy^2-Ny^2)*R^2/8,  R = 1/(Dx*Dy)
#define SXOR2X2_RAT(out, zx, zy)                                         \
    {                                                                    \
        p2 Nx, Dx, Ny, Dy;                                               \
        rat_tanh_nd(zx, Nx, Dx, A6,A5,A4,A3,A2,A1,A0, B3,B2,B1,B0);      \
        rat_tanh_nd(zy, Ny, Dy, A6,A5,A4,A3,A2,A1,A0, B3,B2,B1,B0);      \
        p2 P  = mul2(Dx, Dy);                                            \
        p2 nP = xor2(P, kSGN);                                           \
        p2 R  = rcp_seed(P);                                             \
        R = mul2(R, fma2(nP, R, k2));                                    \
        R = mul2(R, fma2(nP, R, k2));                                    \
        R = mul2(R, fma2(nP, R, k2));                                    \
        p2 R2 = mul2(R, R);                                              \
        p2 t1 = mul2(mul2(Nx, Ny), R);   /* tx*ty  (FIX: R, not R^2) */  \
        p2 pX = add2(Dx, Nx);                                            \
        p2 qX = fma2(Nx, kN1, Dx);                                       \
        p2 pY = add2(Dy, Ny);                                            \
        p2 qY = fma2(Ny, kN1, Dy);                                       \
        p2 AA = mul2(mul2(pX, qX), mul2(pY, qY));                        \
        p2 r  = fma2(t1, kN1, k1);                                       \
        out = fma2(mul2(AA, R2), kN8, r);                                \
    }

// rotate_right(x,63) given u = 2x (bit-identical to R4):
__device__ __forceinline__ p2 rot63u(p2 u) {
    p2 t = trunc2(u);
    p2 f = fma2(t, CN1, u);             // frac(u), exact
    return mul2(fma2(f, C2P64, u), C2N64);
}

// IV: (float)uint64 (RN cast) * 2^-64 (exact)
#define IV0f ((float)7640891576956012808ULL  * 0x1p-64f)
#define IV1f ((float)13503953896175478587ULL * 0x1p-64f)
#define IV2f ((float)4354685564936845355ULL  * 0x1p-64f)
#define IV3f ((float)11912009170470909681ULL * 0x1p-64f)
#define IV4f ((float)5840696475078001361ULL  * 0x1p-64f)
#define IV5f ((float)11170449401992604703ULL * 0x1p-64f)
#define IV6f ((float)2270897969802886507ULL  * 0x1p-64f)
#define IV7f ((float)6620516959819538809ULL  * 0x1p-64f)

// Gf with rot scalings folded (exact pow-2 algebra; bit-identical to R4 on
// the tanh.approx sites). d returned properly scaled; b via rot63.
#define GF(a, b, c, d, x, y)                                             \
    {                                                                    \
        a = sadd_pre(add2(a, b));                                        \
        a = sadd_pre(add2(a, x));                                        \
        p2 d1 = sxor_core(fma2(d, C5, CN2P5), fma2(a, C5, CN2P5));       \
        c = sadd_pre(fma2(d1, C2N32, c));                                \
        p2 b1 = sxor_core(fma2(b, C5, CN2P5), fma2(c, C5, CN2P5));       \
        a = sadd_pre(fma2(b1, C2N24, a));                                \
        a = sadd_pre(add2(a, y));                                        \
        p2 d2 = sxor_core(fma2(d1, C5_32, CN2P5), fma2(a, C5, CN2P5));   \
        d = mul2(d2, C2N16);                                             \
        c = sadd_pre(fma2(d2, C2N16, c));                                \
        p2 u2;                                                           \
        SXOR2X2_RAT(u2, fma2(b1, C5_24, CN2P5), fma2(c, C5, CN2P5));     \
        b = rot63u(u2);                                                  \
    }

__global__ __launch_bounds__(128)
void blake_soft_kernel(const float* __restrict__ msg,
                       float* __restrict__ out, int pairs)
{
    __shared__ p2 sm[16 * 128];          // [word][tid], conflict-free LDS.64
    int tid = threadIdx.x;
    int i = blockIdx.x * blockDim.x + tid;

    if (i < pairs) {
        const float4* mp = reinterpret_cast<const float4*>(msg) + (size_t)i * 8;
        float4 a0 = mp[0], a1 = mp[1], a2 = mp[2], a3 = mp[3];   // elem 2i
        float4 b0 = mp[4], b1 = mp[5], b2 = mp[6], b3 = mp[7];   // elem 2i+1
        sm[ 0*128 + tid] = pk(a0.x, b0.x); sm[ 1*128 + tid] = pk(a0.y, b0.y);
        sm[ 2*128 + tid] = pk(a0.z, b0.z); sm[ 3*128 + tid] = pk(a0.w, b0.w);
        sm[ 4*128 + tid] = pk(a1.x, b1.x); sm[ 5*128 + tid] = pk(a1.y, b1.y);
        sm[ 6*128 + tid] = pk(a1.z, b1.z); sm[ 7*128 + tid] = pk(a1.w, b1.w);
        sm[ 8*128 + tid] = pk(a2.x, b2.x); sm[ 9*128 + tid] = pk(a2.y, b2.y);
        sm[10*128 + tid] = pk(a2.z, b2.z); sm[11*128 + tid] = pk(a2.w, b2.w);
        sm[12*128 + tid] = pk(a3.x, b3.x); sm[13*128 + tid] = pk(a3.y, b3.y);
        sm[14*128 + tid] = pk(a3.z, b3.z); sm[15*128 + tid] = pk(a3.w, b3.w);
    }
    __syncthreads();
    if (i >= pairs) return;

    // broadcast Eigen/helper constants (loop-invariant; UR-promotable)
    const p2 A6 = pk(EA6, EA6), A5 = pk(EA5, EA5), A4 = pk(EA4, EA4);
    const p2 A3 = pk(EA3, EA3), A2 = pk(EA2, EA2), A1 = pk(EA1, EA1);
    const p2 A0 = pk(EA0, EA0);
    const p2 B3 = pk(EB3, EB3), B2 = pk(EB2, EB2), B1 = pk(EB1, EB1);
    const p2 B0 = pk(EB0, EB0);
    const p2 kSGN = SGNM, k2 = C2, k1 = C1, kN1 = CN1, kN8 = CN8;

    const p2 iv0 = pk(IV0f, IV0f), iv1 = pk(IV1f, IV1f);
    const p2 iv2 = pk(IV2f, IV2f), iv3 = pk(IV3f, IV3f);
    const p2 iv4 = pk(IV4f, IV4f), iv5 = pk(IV5f, IV5f);
    const p2 iv6 = pk(IV6f, IV6f), iv7 = pk(IV7f, IV7f);

    p2 s0 = iv0, s1 = iv1, s2 = iv2, s3 = iv3;
    p2 s4 = iv4, s5 = iv5, s6 = iv6, s7 = iv7;

    #pragma unroll 1
    for (int r = 0; r < 10; ++r) {
        p2 v0 = s0,  v1 = s1,  v2  = s2,  v3  = s3;
        p2 v4 = s4,  v5 = s5,  v6  = s6,  v7  = s7;
        p2 v8 = iv0, v9 = iv1, v10 = iv2, v11 = iv3;
        p2 v12 = iv4, v13 = iv5, v14 = iv6, v15 = iv7;

        GF(v0, v4, v8,  v12, sm[ 0*128+tid], sm[ 1*128+tid]);
        GF(v1, v5, v9,  v13, sm[ 2*128+tid], sm[ 3*128+tid]);
        GF(v2, v6, v10, v14, sm[ 4*128+tid], sm[ 5*128+tid]);
        GF(v3, v7, v11, v15, sm[ 6*128+tid], sm[ 7*128+tid]);
        GF(v0, v5, v10, v15, sm[ 8*128+tid], sm[ 9*128+tid]);
        GF(v1, v6, v11, v12, sm[10*128+tid], sm[11*128+tid]);
        GF(v2, v7, v8,  v13, sm[12*128+tid], sm[13*128+tid]);
        GF(v3, v4, v9,  v14, sm[14*128+tid], sm[15*128+tid]);

        s0 = sxor_core(fma2(v0, C5, CN2P5), fma2(v8,  C5, CN2P5));
        s1 = sxor_core(fma2(v1, C5, CN2P5), fma2(v9,  C5, CN2P5));
        s2 = sxor_core(fma2(v2, C5, CN2P5), fma2(v10, C5, CN2P5));
        s3 = sxor_core(fma2(v3, C5, CN2P5), fma2(v11, C5, CN2P5));
        s4 = sxor_core(fma2(v4, C5, CN2P5), fma2(v12, C5, CN2P5));
        s5 = sxor_core(fma2(v5, C5, CN2P5), fma2(v13, C5, CN2P5));
        s6 = sxor_core(fma2(v6, C5, CN2P5), fma2(v14, C5, CN2P5));
        s7 = sxor_core(fma2(v7, C5, CN2P5), fma2(v15, C5, CN2P5));
    }

    float e0, f0, e1, f1, e2, f2, e3, f3;
    float e4, f4, e5, f5, e6, f6, e7, f7;
    upk(s0, e0, f0); upk(s1, e1, f1); upk(s2, e2, f2); upk(s3, e3, f3);
    upk(s4, e4, f4); upk(s5, e5, f5); upk(s6, e6, f6); upk(s7, e7, f7);

    float4* op = reinterpret_cast<float4*>(out) + (size_t)i * 4;
    op[0] = make_float4(e0, e1, e2, e3);
    op[1] = make_float4(e4, e5, e6, e7);
    op[2] = make_float4(f0, f1, f2, f3);
    op[3] = make_float4(f4, f5, f6, f7);
}

extern "C" void kernel_launch(void* const* d_in, const int* in_sizes, int n_in,
                              void* d_out, int out_size)
{
    const float* msg = (const float*)d_in[0];
    float* out = (float*)d_out;
    int batch = in_sizes[0] / 16;
    int pairs = batch / 2;              // batch is even (2,000,000)
    int threads = 128;
    int blocks = (pairs + threads - 1) / threads;
    blake_soft_kernel<<<blocks, threads>>>(msg, out, pairs);
}

// round 9
// speedup vs baseline: 1.2078x; 1.2078x over previous
#include <cuda_runtime.h>
#include <math.h>

// ---------------------------------------------------------------------------
// Round 7: structural tanh elimination via exact f32 range analysis of the
// reference. Sites where the sigmoid argument provably collapses in f32:
//  - d-xor#2: x = d1*2^-32 -> fl(x-0.5) == -0.5 ALWAYS -> xs = sigma(-5) const
//  - d-xor#1 in G1-G4: x = iv (const) -> per-column const (tanhf, once)
//  - d-xor#1 in G5-G8 (x = d2*2^-16) and rot63-feeder x (b1*2^-24):
//    tanh(-2.5 + 5x) = ct + lam*x, linearization err <= 1.5e-10
//  - final xors s4..7: y = v12..15 tiny -> same linearization
// tanh2 per element: 1280 -> 1000. All other ops bit-identical to R4.
// ---------------------------------------------------------------------------

typedef unsigned long long p2;   // packed float2 in one 64-bit register pair

#define BCST(h) ((((p2)(h))<<32) | (p2)(h))

#define C5     BCST(0x40A00000u)  //  5.0
#define CN5    BCST(0xC0A00000u)  // -5.0
#define CN2P5  BCST(0xC0200000u)  // -2.5
#define CH     BCST(0x3F000000u)  //  0.5
#define CNH    BCST(0xBF000000u)  // -0.5
#define C1     BCST(0x3F800000u)  //  1.0
#define CN1    BCST(0xBF800000u)  // -1.0
#define CN16   BCST(0xBD800000u)  // -1/16
#define CN8    BCST(0xBE000000u)  // -1/8
#define C2P64  BCST(0x5F800000u)  //  2^64
#define C2N64  BCST(0x1F800000u)  //  2^-64
#define C2N32  BCST(0x2F800000u)  //  2^-32
#define C2N24  BCST(0x33800000u)  //  2^-24
#define C2N16  BCST(0x37800000u)  //  2^-16

#define CTF    (-0.98661430f)                 // tanh(-2.5)
#define LAMF   (0.13296113f)                  // 5*sech^2(2.5)
#define LAM24F (0.13296113f * 0x1p-24f)       // lam * 2^-24 (b1-scaled x)
#define BC0F   (0.49330715f)                  // -ct/2
#define CC0F   (0.0016620142f)                // (1-ct^2)/16

__device__ __forceinline__ p2 pk(float lo, float hi) {
    p2 r; asm("mov.b64 %0, {%1, %2};" : "=l"(r) : "f"(lo), "f"(hi)); return r;
}
__device__ __forceinline__ void upk(p2 v, float& lo, float& hi) {
    asm("mov.b64 {%0, %1}, %2;" : "=f"(lo), "=f"(hi) : "l"(v));
}
__device__ __forceinline__ p2 fma2(p2 a, p2 b, p2 c) {
    p2 r; asm("fma.rn.f32x2 %0, %1, %2, %3;" : "=l"(r) : "l"(a), "l"(b), "l"(c)); return r;
}
__device__ __forceinline__ p2 add2(p2 a, p2 b) {
    p2 r; asm("add.rn.f32x2 %0, %1, %2;" : "=l"(r) : "l"(a), "l"(b)); return r;
}
__device__ __forceinline__ p2 mul2(p2 a, p2 b) {
    p2 r; asm("mul.rn.f32x2 %0, %1, %2;" : "=l"(r) : "l"(a), "l"(b)); return r;
}
__device__ __forceinline__ p2 tanh2(p2 z) {
    float a, b; upk(z, a, b);
    asm("tanh.approx.f32 %0, %0;" : "+f"(a));
    asm("tanh.approx.f32 %0, %0;" : "+f"(b));
    return pk(a, b);
}
__device__ __forceinline__ p2 trunc2(p2 z) {
    float a, b; upk(z, a, b);
    return pk(truncf(a), truncf(b));
}

__device__ __forceinline__ p2 sadd_pre(p2 s) {
    p2 t = tanh2(fma2(s, C5, CN5));
    return fma2(t, CNH, add2(s, CNH));
}

__device__ __forceinline__ p2 sxor_core(p2 zx, p2 zy) {
    p2 tx = tanh2(zx);
    p2 ty = tanh2(zy);
    p2 r1 = fma2(mul2(tx, ty), CNH, CH);
    p2 a  = fma2(tx, tx, CN1);
    p2 b  = fma2(ty, ty, CN1);
    return fma2(mul2(a, b), CN16, r1);
}

#define XOR_CONSTX(out, ysrc, Bc, Cc)                                    \
    {                                                                    \
        p2 _ty = tanh2(fma2(ysrc, C5, CN2P5));                           \
        p2 _by = fma2(_ty, _ty, CN1);                                    \
        out = fma2(_by, Cc, fma2(_ty, Bc, CH));                          \
    }

#define XOR_LINX(out, xs, lam, ysrc)                                     \
    {                                                                    \
        p2 _tx = fma2(xs, lam, kCT);                                     \
        p2 _ty = tanh2(fma2(ysrc, C5, CN2P5));                           \
        p2 _ax = fma2(_tx, _tx, CN1);                                    \
        p2 _by = fma2(_ty, _ty, CN1);                                    \
        out = fma2(mul2(_ax, _by), CN16, fma2(mul2(_tx, _ty), CNH, CH)); \
    }

#define XOR2X_LINX(out, xs, lam, ysrc)                                   \
    {                                                                    \
        p2 _tx = fma2(xs, lam, kCT);                                     \
        p2 _ty = tanh2(fma2(ysrc, C5, CN2P5));                           \
        p2 _ax = fma2(_tx, _tx, CN1);                                    \
        p2 _by = fma2(_ty, _ty, CN1);                                    \
        out = fma2(mul2(_ax, _by), CN8, fma2(mul2(_tx, _ty), CN1, C1));  \
    }

__device__ __forceinline__ p2 rot63u(p2 u) {
    p2 t = trunc2(u);
    p2 f = fma2(t, CN1, u);             // frac(u), exact
    return mul2(fma2(f, C2P64, u), C2N64);
}

#define IV0f ((float)7640891576956012808ULL  * 0x1p-64f)
#define IV1f ((float)13503953896175478587ULL * 0x1p-64f)
#define IV2f ((float)4354685564936845355ULL  * 0x1p-64f)
#define IV3f ((float)11912009170470909681ULL * 0x1p-64f)
#define IV4f ((float)5840696475078001361ULL  * 0x1p-64f)
#define IV5f ((float)11170449401992604703ULL * 0x1p-64f)
#define IV6f ((float)2270897969802886507ULL  * 0x1p-64f)
#define IV7f ((float)6620516959819538809ULL  * 0x1p-64f)

#define GF_A(a, b, c, dout, Bc, Cc, x, y)                                \
    {                                                                    \
        a = sadd_pre(add2(a, b));                                        \
        a = sadd_pre(add2(a, x));                                        \
        p2 d1; XOR_CONSTX(d1, a, Bc, Cc);                                \
        c = sadd_pre(fma2(d1, C2N32, c));                                \
        p2 b1 = sxor_core(fma2(b, C5, CN2P5), fma2(c, C5, CN2P5));       \
        a = sadd_pre(fma2(b1, C2N24, a));                                \
        a = sadd_pre(add2(a, y));                                        \
        p2 d2; XOR_CONSTX(d2, a, kBC0, kCC0);                            \
        dout = mul2(d2, C2N16);                                          \
        c = sadd_pre(fma2(d2, C2N16, c));                                \
        p2 u2; XOR2X_LINX(u2, b1, kLAM24, c);                            \
        b = rot63u(u2);                                                  \
    }

#define GF_B(a, b, c, d, x, y)                                           \
    {                                                                    \
        a = sadd_pre(add2(a, b));                                        \
        a = sadd_pre(add2(a, x));                                        \
        p2 d1; XOR_LINX(d1, d, kLAM, a);                                 \
        c = sadd_pre(fma2(d1, C2N32, c));                                \
        p2 b1 = sxor_core(fma2(b, C5, CN2P5), fma2(c, C5, CN2P5));       \
        a = sadd_pre(fma2(b1, C2N24, a));                                \
        a = sadd_pre(add2(a, y));                                        \
        p2 d2; XOR_CONSTX(d2, a, kBC0, kCC0);                            \
        d = mul2(d2, C2N16);                                             \
        c = sadd_pre(fma2(d2, C2N16, c));                                \
        p2 u2; XOR2X_LINX(u2, b1, kLAM24, c);                            \
        b = rot63u(u2);                                                  \
    }

__global__ __launch_bounds__(128)
void blake_soft_kernel(const float* __restrict__ msg,
                       float* __restrict__ out, int pairs)
{
    __shared__ p2 sm[16 * 128];
    int tid = threadIdx.x;
    int i = blockIdx.x * blockDim.x + tid;

    if (i < pairs) {
        const float4* mp = reinterpret_cast<const float4*>(msg) + (size_t)i * 8;
        float4 a0 = mp[0], a1 = mp[1], a2 = mp[2], a3 = mp[3];
        float4 b0 = mp[4], b1 = mp[5], b2 = mp[6], b3 = mp[7];
        sm[ 0*128 + tid] = pk(a0.x, b0.x); sm[ 1*128 + tid] = pk(a0.y, b0.y);
        sm[ 2*128 + tid] = pk(a0.z, b0.z); sm[ 3*128 + tid] = pk(a0.w, b0.w);
        sm[ 4*128 + tid] = pk(a1.x, b1.x); sm[ 5*128 + tid] = pk(a1.y, b1.y);
        sm[ 6*128 + tid] = pk(a1.z, b1.z); sm[ 7*128 + tid] = pk(a1.w, b1.w);
        sm[ 8*128 + tid] = pk(a2.x, b2.x); sm[ 9*128 + tid] = pk(a2.y, b2.y);
        sm[10*128 + tid] = pk(a2.z, b2.z); sm[11*128 + tid] = pk(a2.w, b2.w);
        sm[12*128 + tid] = pk(a3.x, b3.x); sm[13*128 + tid] = pk(a3.y, b3.y);
        sm[14*128 + tid] = pk(a3.z, b3.z); sm[15*128 + tid] = pk(a3.w, b3.w);
    }
    __syncthreads();
    if (i >= pairs) return;

    const p2 kCT    = pk(CTF, CTF);
    const p2 kLAM   = pk(LAMF, LAMF);
    const p2 kLAM24 = pk(LAM24F, LAM24F);
    const p2 kBC0   = pk(BC0F, BC0F);
    const p2 kCC0   = pk(CC0F, CC0F);

    // per-column consts for G1-G4 first d-xor: tx = tanh(5*iv - 2.5), once
    float t4 = tanhf(fmaf(IV4f, 5.0f, -2.5f));
    float t5 = tanhf(fmaf(IV5f, 5.0f, -2.5f));
    float t6 = tanhf(fmaf(IV6f, 5.0f, -2.5f));
    float t7 = tanhf(fmaf(IV7f, 5.0f, -2.5f));
    float b4 = -0.5f*t4, c4 = (1.0f - t4*t4)*0.0625f;
    float b5 = -0.5f*t5, c5 = (1.0f - t5*t5)*0.0625f;
    float b6 = -0.5f*t6, c6 = (1.0f - t6*t6)*0.0625f;
    float b7 = -0.5f*t7, c7 = (1.0f - t7*t7)*0.0625f;
    const p2 kBc4 = pk(b4, b4), kCc4 = pk(c4, c4);
    const p2 kBc5 = pk(b5, b5), kCc5 = pk(c5, c5);
    const p2 kBc6 = pk(b6, b6), kCc6 = pk(c6, c6);
    const p2 kBc7 = pk(b7, b7), kCc7 = pk(c7, c7);

    const p2 iv0 = pk(IV0f, IV0f), iv1 = pk(IV1f, IV1f);
    const p2 iv2 = pk(IV2f, IV2f), iv3 = pk(IV3f, IV3f);
    const p2 iv4 = pk(IV4f, IV4f), iv5 = pk(IV5f, IV5f);
    const p2 iv6 = pk(IV6f, IV6f), iv7 = pk(IV7f, IV7f);

    p2 s0 = iv0, s1 = iv1, s2 = iv2, s3 = iv3;
    p2 s4 = iv4, s5 = iv5, s6 = iv6, s7 = iv7;

    #pragma unroll 1
    for (int r = 0; r < 10; ++r) {
        p2 v0 = s0,  v1 = s1,  v2  = s2,  v3  = s3;
        p2 v4 = s4,  v5 = s5,  v6  = s6,  v7  = s7;
        p2 v8 = iv0, v9 = iv1, v10 = iv2, v11 = iv3;
        p2 d12, d13, d14, d15;

        GF_A(v0, v4, v8,  d12, kBc4, kCc4, sm[ 0*128+tid], sm[ 1*128+tid]);
        GF_A(v1, v5, v9,  d13, kBc5, kCc5, sm[ 2*128+tid], sm[ 3*128+tid]);
        GF_A(v2, v6, v10, d14, kBc6, kCc6, sm[ 4*128+tid], sm[ 5*128+tid]);
        GF_A(v3, v7, v11, d15, kBc7, kCc7, sm[ 6*128+tid], sm[ 7*128+tid]);
        GF_B(v0, v5, v10, d15, sm[ 8*128+tid], sm[ 9*128+tid]);
        GF_B(v1, v6, v11, d12, sm[10*128+tid], sm[11*128+tid]);
        GF_B(v2, v7, v8,  d13, sm[12*128+tid], sm[13*128+tid]);
        GF_B(v3, v4, v9,  d14, sm[14*128+tid], sm[15*128+tid]);

        s0 = sxor_core(fma2(v0, C5, CN2P5), fma2(v8,  C5, CN2P5));
        s1 = sxor_core(fma2(v1, C5, CN2P5), fma2(v9,  C5, CN2P5));
        s2 = sxor_core(fma2(v2, C5, CN2P5), fma2(v10, C5, CN2P5));
        s3 = sxor_core(fma2(v3, C5, CN2P5), fma2(v11, C5, CN2P5));
        XOR_LINX(s4, d12, kLAM, v4);
        XOR_LINX(s5, d13, kLAM, v5);
        XOR_LINX(s6, d14, kLAM, v6);
        XOR_LINX(s7, d15, kLAM, v7);
    }

    float e0, f0, e1, f1, e2, f2, e3, f3;
    float e4, f4, e5, f5, e6, f6, e7, f7;
    upk(s0, e0, f0); upk(s1, e1, f1); upk(s2, e2, f2); upk(s3, e3, f3);
    upk(s4, e4, f4); upk(s5, e5, f5); upk(s6, e6, f6); upk(s7, e7, f7);

    float4* op = reinterpret_cast<float4*>(out) + (size_t)i * 4;
    op[0] = make_float4(e0, e1, e2, e3);
    op[1] = make_float4(e4, e5, e6, e7);
    op[2] = make_float4(f0, f1, f2, f3);
    op[3] = make_float4(f4, f5, f6, f7);
}

extern "C" void kernel_launch(void* const* d_in, const int* in_sizes, int n_in,
                              void* d_out, int out_size)
{
    const float* msg = (const float*)d_in[0];
    float* out = (float*)d_out;
    int batch = in_sizes[0] / 16;
    int pairs = batch / 2;
    int threads = 128;
    int blocks = (pairs + threads - 1) / threads;
    blake_soft_kernel<<<blocks, threads>>>(msg, out, pairs);
}